// round 10
// baseline (speedup 1.0000x reference)
#include <cuda_runtime.h>

// Problem constants: N=1024 agents, H=64 hidden.
#define Nn 1024
#define Hh 64
#define EE (Nn * (Nn - 1))   // 1047552 edges

#define TSI 32
#define TSJ 32
#define TPAD 76

// Factored first layer + relu-elimination scalars:
//   gA[i][k] = b1[k] + sum_c emb[i][c] * W1[c][k]
//   gB[j][k] =         sum_c emb[j][c] * W1[64+c][k]
//   gGamma[i] = b2 + 0.5 * <W2, gA[i]>,   gDelta[j] = 0.5 * <W2, gB[j]>
__device__ float gA[Nn * Hh];
__device__ float gB[Nn * Hh];
__device__ float gGamma[Nn];
__device__ float gDelta[Nn];
__device__ int gReady;   // zero-initialized; reset by last CTA each launch
__device__ int gDone;

// ---- packed f32x2 add (sm_10x) ---------------------------------------------
__device__ __forceinline__ float2 add2(float2 a, float2 b) {
    float2 d;
    asm("add.rn.f32x2 %0, %1, %2;"
        : "=l"(*reinterpret_cast<unsigned long long*>(&d))
        : "l"(*reinterpret_cast<const unsigned long long*>(&a)),
          "l"(*reinterpret_cast<const unsigned long long*>(&b)));
    return d;
}

struct PairSmem {
    float sA[TSI * TPAD];
    float sB[TSJ * TPAD];
    float sW2[64];        // pre-scaled by 0.5
    float sGam[TSI];
    float sDel[TSJ];
};
union Smem {
    float w1[128 * 64];   // 32 KB, prep phase only (CTAs 0..255)
    PairSmem p;           // ~20 KB, pair phase
};

// ---------------------------------------------------------------------------
// ONE fused kernel. Grid 1024 CTAs x 128 threads, bounds(128,7).
//  Phase A (CTAs 0..255): prep 4 rows each (W1 staged in smem) -> gA/gB/γ/δ,
//    then fence + gReady++.
//  Meanwhile ALL CTAs: write their tile's i/j index planes (prep-independent)
//    and stage sW2, then spin (acquire) until gReady==256.
//  Phase B: round-9 pair compute: x = γ_i + δ_j + Σ (w_k/2)|A_ik+B_jk|,
//    2x4 micro-tile, conflict-free TPAD=76 SMEM, weight-plane stores.
//  Cleanup: last CTA (gDone==1024) resets the flags -> replay-deterministic.
//  Deadlock-free even without full residency: prep CTAs are the lowest bids
//  (wave-1), and the reset waits for every CTA to pass the barrier.
// ---------------------------------------------------------------------------
__global__ void __launch_bounds__(128, 7)
fused_kernel(const float* __restrict__ emb, const float* __restrict__ W1,
             const float* __restrict__ b1, const float* __restrict__ W2,
             const float* __restrict__ b2ptr, float* __restrict__ out) {
    __shared__ Smem sm;

    const int t = threadIdx.x;
    const int bid = blockIdx.x;
    const int tx = t & 7;
    const int ty = t >> 3;
    const int i0 = (bid >> 5) * TSI;
    const int j0 = (bid & 31) * TSJ;

    // ---------------- Phase A: prep (CTAs 0..255, 4 rows each) -------------
    if (bid < 256) {
        // Stage W1 (32 KB): 2048 float4 / 128 threads = 16 each, coalesced.
#pragma unroll
        for (int q = t; q < 2048; q += 128)
            reinterpret_cast<float4*>(sm.w1)[q] = reinterpret_cast<const float4*>(W1)[q];
        __syncthreads();

        const int wid = t >> 5;
        const int lane = t & 31;
        const int row = bid * 4 + wid;
        const int m = lane * 4;
        const int half = m >> 6;
        const int k = m & 63;
        const float* w1base = sm.w1 + half * Hh * Hh;

        float acc0 = 0.f, acc1 = 0.f, acc2 = 0.f, acc3 = 0.f;
#pragma unroll
        for (int c = 0; c < Hh; c += 4) {
            const float4 e4 = *reinterpret_cast<const float4*>(emb + row * Hh + c);
            const float4 w0 = *reinterpret_cast<const float4*>(w1base + (c + 0) * Hh + k);
            const float4 w1v = *reinterpret_cast<const float4*>(w1base + (c + 1) * Hh + k);
            const float4 w2v = *reinterpret_cast<const float4*>(w1base + (c + 2) * Hh + k);
            const float4 w3v = *reinterpret_cast<const float4*>(w1base + (c + 3) * Hh + k);
            acc0 = fmaf(e4.x, w0.x, acc0); acc0 = fmaf(e4.y, w1v.x, acc0);
            acc0 = fmaf(e4.z, w2v.x, acc0); acc0 = fmaf(e4.w, w3v.x, acc0);
            acc1 = fmaf(e4.x, w0.y, acc1); acc1 = fmaf(e4.y, w1v.y, acc1);
            acc1 = fmaf(e4.z, w2v.y, acc1); acc1 = fmaf(e4.w, w3v.y, acc1);
            acc2 = fmaf(e4.x, w0.z, acc2); acc2 = fmaf(e4.y, w1v.z, acc2);
            acc2 = fmaf(e4.z, w2v.z, acc2); acc2 = fmaf(e4.w, w3v.z, acc2);
            acc3 = fmaf(e4.x, w0.w, acc3); acc3 = fmaf(e4.y, w1v.w, acc3);
            acc3 = fmaf(e4.z, w2v.w, acc3); acc3 = fmaf(e4.w, w3v.w, acc3);
        }

        float4 o;
        if (half == 0) {
            const float4 bb = *reinterpret_cast<const float4*>(b1 + k);
            o.x = acc0 + bb.x; o.y = acc1 + bb.y; o.z = acc2 + bb.z; o.w = acc3 + bb.w;
            *reinterpret_cast<float4*>(&gA[row * Hh + k]) = o;
        } else {
            o.x = acc0; o.y = acc1; o.z = acc2; o.w = acc3;
            *reinterpret_cast<float4*>(&gB[row * Hh + k]) = o;
        }

        // gamma/delta: dot quad with W2, butterfly-reduce within 16-lane halves.
        const float4 wv = *reinterpret_cast<const float4*>(W2 + k);
        float part = o.x * wv.x + o.y * wv.y + o.z * wv.z + o.w * wv.w;
#pragma unroll
        for (int off = 8; off > 0; off >>= 1)
            part += __shfl_xor_sync(0xffffffffu, part, off);
        if (lane == 0)  gGamma[row] = b2ptr[0] + 0.5f * part;
        if (lane == 16) gDelta[row] = 0.5f * part;

        __threadfence();
        __syncthreads();
        if (t == 0) atomicAdd(&gReady, 1);
    }

    // ------- Prep-independent work (overlaps phase A on non-prep CTAs) -----
    // Index planes for this tile: out[e] = i, out[E+e] = j.
#pragma unroll
    for (int ii = 0; ii < 2; ii++) {
        const int i = i0 + ty + 16 * ii;
#pragma unroll
        for (int jj = 0; jj < 4; jj++) {
            const int j = j0 + tx + 8 * jj;
            if (j == i) continue;
            const int e = i * (Nn - 1) + j - (j > i ? 1 : 0);
            out[e] = (float)i;
            out[EE + e] = (float)j;
        }
    }
    if (t < 64) sm.p.sW2[t] = 0.5f * W2[t];   // safe: prep CTAs are past w1 use

    // ---------------- Device-wide barrier: wait for all prep --------------
    if (t == 0) {
        int v;
        do {
            asm volatile("ld.acquire.gpu.b32 %0, [%1];" : "=r"(v) : "l"(&gReady));
            if (v < 256) __nanosleep(128);
        } while (v < 256);
    }
    __syncthreads();

    // ---------------- Phase B: pair compute (round-9 form) ----------------
    if (t < 32)       sm.p.sGam[t] = gGamma[i0 + t];
    else if (t < 64)  sm.p.sDel[t - 32] = gDelta[j0 + (t - 32)];
#pragma unroll
    for (int q = t; q < 1024; q += 128) {
        if (q < 512) {
            const int r = q >> 4, c4 = (q & 15) * 4;
            *reinterpret_cast<float4*>(&sm.p.sA[r * TPAD + c4]) =
                *reinterpret_cast<const float4*>(&gA[(i0 + r) * Hh + c4]);
        } else {
            const int q2 = q - 512;
            const int r = q2 >> 4, c4 = (q2 & 15) * 4;
            *reinterpret_cast<float4*>(&sm.p.sB[r * TPAD + c4]) =
                *reinterpret_cast<const float4*>(&gB[(j0 + r) * Hh + c4]);
        }
    }
    __syncthreads();

    float acc[2][4] = {};
    const float* aRow0 = &sm.p.sA[ty * TPAD];
    const float* aRow1 = &sm.p.sA[(ty + 16) * TPAD];
    const float* bRow0 = &sm.p.sB[tx * TPAD];
    const float* bRow1 = &sm.p.sB[(tx + 8) * TPAD];
    const float* bRow2 = &sm.p.sB[(tx + 16) * TPAD];
    const float* bRow3 = &sm.p.sB[(tx + 24) * TPAD];

#pragma unroll
    for (int k = 0; k < Hh; k += 4) {
        const float4 wq = *reinterpret_cast<const float4*>(&sm.p.sW2[k]);
        const float4 av[2] = {
            *reinterpret_cast<const float4*>(aRow0 + k),
            *reinterpret_cast<const float4*>(aRow1 + k)
        };
        const float4 bv[4] = {
            *reinterpret_cast<const float4*>(bRow0 + k),
            *reinterpret_cast<const float4*>(bRow1 + k),
            *reinterpret_cast<const float4*>(bRow2 + k),
            *reinterpret_cast<const float4*>(bRow3 + k)
        };
#pragma unroll
        for (int ii = 0; ii < 2; ii++) {
            const float2 a01 = *reinterpret_cast<const float2*>(&av[ii].x);
            const float2 a23 = *reinterpret_cast<const float2*>(&av[ii].z);
#pragma unroll
            for (int jj = 0; jj < 4; jj++) {
                const float2 b01 = *reinterpret_cast<const float2*>(&bv[jj].x);
                const float2 b23 = *reinterpret_cast<const float2*>(&bv[jj].z);
                const float2 t01 = add2(a01, b01);
                const float2 t23 = add2(a23, b23);
                float a = acc[ii][jj];
                a = fmaf(fabsf(t01.x), wq.x, a);
                a = fmaf(fabsf(t01.y), wq.y, a);
                a = fmaf(fabsf(t23.x), wq.z, a);
                a = fmaf(fabsf(t23.y), wq.w, a);
                acc[ii][jj] = a;
            }
        }
    }

#pragma unroll
    for (int ii = 0; ii < 2; ii++) {
        const int i = i0 + ty + 16 * ii;
        const float gi = sm.p.sGam[ty + 16 * ii];
#pragma unroll
        for (int jj = 0; jj < 4; jj++) {
            const int j = j0 + tx + 8 * jj;
            if (j == i) continue;
            const int e = i * (Nn - 1) + j - (j > i ? 1 : 0);
            const float x = acc[ii][jj] + gi + sm.p.sDel[tx + 8 * jj];
            out[2 * EE + e] = 1.0f / (1.0f + __expf(-x));
        }
    }

    // ---------------- Flag reset (replay determinism) ----------------------
    if (t == 0) {
        const int d = atomicAdd(&gDone, 1);
        if (d == Nn - 1) {        // last of 1024 CTAs: everyone passed barrier
            gReady = 0;
            gDone = 0;
            __threadfence();
        }
    }
}

extern "C" void kernel_launch(void* const* d_in, const int* in_sizes, int n_in,
                              void* d_out, int out_size) {
    const float* emb = (const float*)d_in[0];  // [1024, 64]
    const float* W1  = (const float*)d_in[1];  // [128, 64]
    const float* b1  = (const float*)d_in[2];  // [64]
    const float* W2  = (const float*)d_in[3];  // [64, 1]
    const float* b2  = (const float*)d_in[4];  // [1]
    float* out = (float*)d_out;

    fused_kernel<<<1024, 128>>>(emb, W1, b1, W2, b2, out);
}

// round 11
// speedup vs baseline: 1.2429x; 1.2429x over previous
#include <cuda_runtime.h>

// Problem constants: N=1024 agents, H=64 hidden.
#define Nn 1024
#define Hh 64
#define EE (Nn * (Nn - 1))   // 1047552 edges

// Factored first layer + relu-elimination scalars:
//   gA[i][k] = b1[k] + sum_c emb[i][c] * W1[c][k]
//   gB[j][k] =         sum_c emb[j][c] * W1[64+c][k]
//   gGamma[i] = b2 + 0.5 * <W2, gA[i]>,   gDelta[j] = 0.5 * <W2, gB[j]>
__device__ float gA[Nn * Hh];
__device__ float gB[Nn * Hh];
__device__ float gGamma[Nn];
__device__ float gDelta[Nn];

// ---- packed f32x2 add (sm_10x) ---------------------------------------------
__device__ __forceinline__ float2 add2(float2 a, float2 b) {
    float2 d;
    asm("add.rn.f32x2 %0, %1, %2;"
        : "=l"(*reinterpret_cast<unsigned long long*>(&d))
        : "l"(*reinterpret_cast<const unsigned long long*>(&a)),
          "l"(*reinterpret_cast<const unsigned long long*>(&b)));
    return d;
}

// ---------------------------------------------------------------------------
// Kernel 1 (unchanged from round 9): gA/gB = emb @ [W1_top | W1_bot]
// (W1 staged in SMEM), plus gGamma/gDelta via in-warp dot + butterfly reduce.
// 128 CTAs x 256 threads; warp = one emb row.
// ---------------------------------------------------------------------------
__global__ void __launch_bounds__(256) prep_kernel(const float* __restrict__ emb,
                                                   const float* __restrict__ W1,
                                                   const float* __restrict__ b1,
                                                   const float* __restrict__ W2,
                                                   const float* __restrict__ b2ptr) {
    __shared__ float sW1[128 * 64];   // 32 KB

    const int t = threadIdx.x;
#pragma unroll
    for (int q = t; q < 2048; q += 256)
        reinterpret_cast<float4*>(sW1)[q] = reinterpret_cast<const float4*>(W1)[q];
    __syncthreads();

    const int row = blockIdx.x * 8 + (t >> 5);
    const int lane = t & 31;
    const int m = lane * 4;
    const int half = m >> 6;
    const int k = m & 63;
    const float* w1base = sW1 + half * Hh * Hh;

    float acc0 = 0.f, acc1 = 0.f, acc2 = 0.f, acc3 = 0.f;
#pragma unroll
    for (int c = 0; c < Hh; c += 4) {
        const float4 e4 = *reinterpret_cast<const float4*>(emb + row * Hh + c);
        const float4 w0 = *reinterpret_cast<const float4*>(w1base + (c + 0) * Hh + k);
        const float4 w1v = *reinterpret_cast<const float4*>(w1base + (c + 1) * Hh + k);
        const float4 w2v = *reinterpret_cast<const float4*>(w1base + (c + 2) * Hh + k);
        const float4 w3v = *reinterpret_cast<const float4*>(w1base + (c + 3) * Hh + k);
        acc0 = fmaf(e4.x, w0.x, acc0); acc0 = fmaf(e4.y, w1v.x, acc0);
        acc0 = fmaf(e4.z, w2v.x, acc0); acc0 = fmaf(e4.w, w3v.x, acc0);
        acc1 = fmaf(e4.x, w0.y, acc1); acc1 = fmaf(e4.y, w1v.y, acc1);
        acc1 = fmaf(e4.z, w2v.y, acc1); acc1 = fmaf(e4.w, w3v.y, acc1);
        acc2 = fmaf(e4.x, w0.z, acc2); acc2 = fmaf(e4.y, w1v.z, acc2);
        acc2 = fmaf(e4.z, w2v.z, acc2); acc2 = fmaf(e4.w, w3v.z, acc2);
        acc3 = fmaf(e4.x, w0.w, acc3); acc3 = fmaf(e4.y, w1v.w, acc3);
        acc3 = fmaf(e4.z, w2v.w, acc3); acc3 = fmaf(e4.w, w3v.w, acc3);
    }

    float4 o;
    if (half == 0) {
        const float4 bb = *reinterpret_cast<const float4*>(b1 + k);
        o.x = acc0 + bb.x; o.y = acc1 + bb.y; o.z = acc2 + bb.z; o.w = acc3 + bb.w;
        *reinterpret_cast<float4*>(&gA[row * Hh + k]) = o;
    } else {
        o.x = acc0; o.y = acc1; o.z = acc2; o.w = acc3;
        *reinterpret_cast<float4*>(&gB[row * Hh + k]) = o;
    }

    const float4 wv = *reinterpret_cast<const float4*>(W2 + k);
    float part = o.x * wv.x + o.y * wv.y + o.z * wv.z + o.w * wv.w;
#pragma unroll
    for (int off = 8; off > 0; off >>= 1)
        part += __shfl_xor_sync(0xffffffffu, part, off);
    if (lane == 0)  gGamma[row] = b2ptr[0] + 0.5f * part;
    if (lane == 16) gDelta[row] = 0.5f * part;
}

// ---------------------------------------------------------------------------
// Kernel 2: per-pair MLP, relu eliminated:
//   x(i,j) = gGamma[i] + gDelta[j] + sum_k (W2[k]/2) * |A_ik + B_jk|
// Grid 32x32 = 1024 CTAs, **64 threads**, 4x4 micro-tile (16 pairs/thread):
//   tx = t&7, ty = t>>3 (0..7);  i = i0 + ty + 8*ii (ii<4),
//   j = j0 + tx + 8*jj (jj<4).
// Per 4-k chunk per thread: 9 LDS.128 feed 16 pairs -> 2.25 LDS-bytes/pair/k
// (36% less crossbar traffic than the 2x4 tile), 16 independent FFMA chains.
// Bank analysis (TPAD=76, quad = 12*row mod 32): B rows tx+8jj -> 8 distinct
// quads; A rows (4 consecutive ty per warp) -> 4 distinct quads, 8-lane
// broadcast. All LDS.128 conflict-free.
// __launch_bounds__(64,11): reg cap 90 (no spills), smem 20KB*11 = 220KB/SM.
// ---------------------------------------------------------------------------
#define TSI 32
#define TSJ 32
#define TPAD 76

__global__ void __launch_bounds__(64, 11) pair_kernel(const float* __restrict__ W2,
                                                      float* __restrict__ out) {
    __shared__ float sA[TSI * TPAD];
    __shared__ float sB[TSJ * TPAD];
    __shared__ float sW2[64];    // pre-scaled by 0.5
    __shared__ float sGam[TSI];
    __shared__ float sDel[TSJ];

    const int t = threadIdx.x;
    const int tx = t & 7;
    const int ty = t >> 3;
    const int i0 = blockIdx.y * TSI;
    const int j0 = blockIdx.x * TSJ;

    // Cooperative tile loads: sA 512 + sB 512 float4 = 1024 / 64 threads = 16 each.
#pragma unroll
    for (int q = t; q < 1024; q += 64) {
        if (q < 512) {
            const int r = q >> 4, c4 = (q & 15) * 4;
            *reinterpret_cast<float4*>(&sA[r * TPAD + c4]) =
                *reinterpret_cast<const float4*>(&gA[(i0 + r) * Hh + c4]);
        } else {
            const int q2 = q - 512;
            const int r = q2 >> 4, c4 = (q2 & 15) * 4;
            *reinterpret_cast<float4*>(&sB[r * TPAD + c4]) =
                *reinterpret_cast<const float4*>(&gB[(j0 + r) * Hh + c4]);
        }
    }
    sW2[t] = 0.5f * W2[t];
    if (t < 32) sGam[t] = gGamma[i0 + t];
    else        sDel[t - 32] = gDelta[j0 + (t - 32)];
    __syncthreads();

    float acc[4][4] = {};

    const float* aBase = &sA[ty * TPAD];
    const float* bBase = &sB[tx * TPAD];

#pragma unroll
    for (int k = 0; k < Hh; k += 4) {
        const float4 wq = *reinterpret_cast<const float4*>(&sW2[k]);
        float4 av[4], bv[4];
#pragma unroll
        for (int u = 0; u < 4; u++)
            av[u] = *reinterpret_cast<const float4*>(aBase + (8 * u) * TPAD + k);
#pragma unroll
        for (int u = 0; u < 4; u++)
            bv[u] = *reinterpret_cast<const float4*>(bBase + (8 * u) * TPAD + k);

#pragma unroll
        for (int ii = 0; ii < 4; ii++) {
            const float2 a01 = *reinterpret_cast<const float2*>(&av[ii].x);
            const float2 a23 = *reinterpret_cast<const float2*>(&av[ii].z);
#pragma unroll
            for (int jj = 0; jj < 4; jj++) {
                const float2 b01 = *reinterpret_cast<const float2*>(&bv[jj].x);
                const float2 b23 = *reinterpret_cast<const float2*>(&bv[jj].z);
                const float2 t01 = add2(a01, b01);
                const float2 t23 = add2(a23, b23);
                float a = acc[ii][jj];
                a = fmaf(fabsf(t01.x), wq.x, a);
                a = fmaf(fabsf(t01.y), wq.y, a);
                a = fmaf(fabsf(t23.x), wq.z, a);
                a = fmaf(fabsf(t23.y), wq.w, a);
                acc[ii][jj] = a;
            }
        }
    }

#pragma unroll
    for (int ii = 0; ii < 4; ii++) {
        const int i = i0 + ty + 8 * ii;
        const float gi = sGam[ty + 8 * ii];
#pragma unroll
        for (int jj = 0; jj < 4; jj++) {
            const int j = j0 + tx + 8 * jj;
            if (j == i) continue;
            const int e = i * (Nn - 1) + j - (j > i ? 1 : 0);
            const float x = acc[ii][jj] + gi + sDel[tx + 8 * jj];
            out[e] = (float)i;
            out[EE + e] = (float)j;
            out[2 * EE + e] = 1.0f / (1.0f + __expf(-x));
        }
    }
}

extern "C" void kernel_launch(void* const* d_in, const int* in_sizes, int n_in,
                              void* d_out, int out_size) {
    const float* emb = (const float*)d_in[0];  // [1024, 64]
    const float* W1  = (const float*)d_in[1];  // [128, 64]
    const float* b1  = (const float*)d_in[2];  // [64]
    const float* W2  = (const float*)d_in[3];  // [64, 1]
    const float* b2  = (const float*)d_in[4];  // [1]
    float* out = (float*)d_out;

    prep_kernel<<<128, 256>>>(emb, W1, b1, W2, b2);
    pair_kernel<<<dim3(32, 32), 64>>>(W2, out);
}